// round 1
// baseline (speedup 1.0000x reference)
#include <cuda_runtime.h>
#include <cuda_bf16.h>
#include <math.h>

// Problem constants (fixed shapes)
#define B_  1024
#define T_  256
#define C_  64
#define F_  904      // 3*256 + 129 + 7
#define K_  5

// Scratch (device globals: allocation-free contract)
__device__ float g_xT[B_ * C_ * T_];      // x transposed to [b][c][t]
__device__ float g_W3[C_ * F_ * K_];      // W transposed to [c][f][k]
__device__ float g_part[B_ * C_ * K_];    // per-(b,c) partial dot products

// ---------------------------------------------------------------------------
// Kernel 1: transpose W (K_, F_*C_) -> W3 [c][f][k]
// original flat index of (k,f,c) = k*(F_*C_) + f*C_ + c
// ---------------------------------------------------------------------------
__global__ void transposeW(const float* __restrict__ W) {
    int idx = blockIdx.x * blockDim.x + threadIdx.x;
    const int N = K_ * F_ * C_;
    if (idx >= N) return;
    int k = idx / (F_ * C_);
    int r = idx - k * (F_ * C_);
    int f = r >> 6;       // /C_
    int c = r & 63;       // %C_
    g_W3[(c * F_ + f) * K_ + k] = W[idx];
}

// ---------------------------------------------------------------------------
// Kernel 2: transpose x (B,T,C) -> xT (B,C,T), 32x32 smem tiles
// ---------------------------------------------------------------------------
__global__ void transposeX(const float* __restrict__ x) {
    __shared__ float tile[32][33];
    int b  = blockIdx.z;
    int t0 = blockIdx.x * 32;   // 8 tiles over T
    int c0 = blockIdx.y * 32;   // 2 tiles over C
    int tx = threadIdx.x, ty = threadIdx.y;  // (32,8)
    #pragma unroll
    for (int i = 0; i < 32; i += 8) {
        int t = t0 + ty + i, c = c0 + tx;
        tile[ty + i][tx] = x[(b * T_ + t) * C_ + c];
    }
    __syncthreads();
    #pragma unroll
    for (int i = 0; i < 32; i += 8) {
        int c = c0 + ty + i, t = t0 + tx;
        g_xT[(b * C_ + c) * T_ + t] = tile[tx][ty + i];
    }
}

// ---------------------------------------------------------------------------
// Block reduction helpers (128 threads = 4 warps)
// ---------------------------------------------------------------------------
__device__ __forceinline__ float bsum(float v, float* red) {
    int tid = threadIdx.x;
    #pragma unroll
    for (int o = 16; o > 0; o >>= 1) v += __shfl_xor_sync(0xffffffffu, v, o);
    if ((tid & 31) == 0) red[tid >> 5] = v;
    __syncthreads();
    if (tid == 0) red[0] = red[0] + red[1] + red[2] + red[3];
    __syncthreads();
    float r = red[0];
    __syncthreads();
    return r;
}

__device__ __forceinline__ float bmax(float v, float* red) {
    int tid = threadIdx.x;
    #pragma unroll
    for (int o = 16; o > 0; o >>= 1) v = fmaxf(v, __shfl_xor_sync(0xffffffffu, v, o));
    if ((tid & 31) == 0) red[tid >> 5] = v;
    __syncthreads();
    if (tid == 0) red[0] = fmaxf(fmaxf(red[0], red[1]), fmaxf(red[2], red[3]));
    __syncthreads();
    float r = red[0];
    __syncthreads();
    return r;
}

__device__ __forceinline__ int bminI(int v, int* red) {
    int tid = threadIdx.x;
    #pragma unroll
    for (int o = 16; o > 0; o >>= 1) v = min(v, __shfl_xor_sync(0xffffffffu, v, o));
    if ((tid & 31) == 0) red[tid >> 5] = v;
    __syncthreads();
    if (tid == 0) red[0] = min(min(red[0], red[1]), min(red[2], red[3]));
    __syncthreads();
    int r = red[0];
    __syncthreads();
    return r;
}

// ---------------------------------------------------------------------------
// In-place radix-2 DIT FFT-256. Input must be pre-scattered to bit-reversed
// positions. 128 threads, one butterfly per thread per stage.
// Twiddles: twr/twi[j] = exp(-2*pi*i*j/256), j in [0,128).
// ---------------------------------------------------------------------------
__device__ __forceinline__ void fft256(float* __restrict__ fr, float* __restrict__ fi,
                                       const float* __restrict__ twr,
                                       const float* __restrict__ twi) {
    int tid = threadIdx.x;
    #pragma unroll
    for (int len = 2; len <= 256; len <<= 1) {
        int half = len >> 1;
        int grp = tid / half;
        int pos = tid - grp * half;
        int i0 = grp * len + pos;
        int i1 = i0 + half;
        int tws = 256 / len;
        float wr = twr[pos * tws], wi = twi[pos * tws];
        float xr = fr[i1], xi = fi[i1];
        float tr = wr * xr - wi * xi;
        float ti = wr * xi + wi * xr;
        float ur = fr[i0], ui = fi[i0];
        fr[i0] = ur + tr; fi[i0] = ui + ti;
        fr[i1] = ur - tr; fi[i1] = ui - ti;
        __syncthreads();
    }
}

// ---------------------------------------------------------------------------
// Kernel 3: main — one block (128 threads) per (b,c).
// Computes all 904 features and fuses the dot product with W3[c].
// ---------------------------------------------------------------------------
__global__ void __launch_bounds__(128) mainK() {
    __shared__ float fr[256], fi[256];   // FFT work
    __shared__ float sr[256], si[256];   // saved spectrum X
    __shared__ float mg[256];            // magnitudes
    __shared__ float cs[256];            // scan buffer
    __shared__ float twr[128], twi[128]; // twiddles
    __shared__ float red[4];
    __shared__ int   redi[4];

    int tid = threadIdx.x;
    int c = blockIdx.x;
    int b = blockIdx.y;
    const float* __restrict__ xin = g_xT + (b * C_ + c) * T_;
    const float* __restrict__ Wc  = g_W3 + c * F_ * K_;

    // Twiddles
    {
        float s, co;
        sincosf(-6.28318530717958647692f * (float)tid / 256.0f, &s, &co);
        twr[tid] = co; twi[tid] = s;
    }

    int t0 = tid, t1 = tid + 128;
    int r0 = __brev(t0) >> 24, r1 = __brev(t1) >> 24;
    float xv0 = xin[t0], xv1 = xin[t1];

    float mean = bsum(xv0 + xv1, red) * (1.0f / 256.0f);

    // ---- FFT #1: full spectrum X ----
    fr[r0] = xv0; fi[r0] = 0.0f;
    fr[r1] = xv1; fi[r1] = 0.0f;
    __syncthreads();
    fft256(fr, fi, twr, twi);

    // Save X; compute per-bin features + fused dot
    float acc[K_] = {0, 0, 0, 0, 0};
    float sb[K_]  = {0, 0, 0, 0, 0};   // bicoh partial (missing 1/||mag|| factor)
    float lsm = 0, lsm2 = 0, lsfm = 0, lpk = 0, lur = 0, lui = 0;
    #pragma unroll
    for (int e = 0; e < 2; e++) {
        int t = tid + e * 128;
        float re = fr[t], im = fi[t];
        sr[t] = re; si[t] = im;
        float m = sqrtf(re * re + im * im);
        mg[t] = m;
        float ph = atan2f(im, re);
        float fq = (t < 128) ? (float)t : (float)(t - 256);
        lsm += m; lsm2 += m * m; lsfm += fq * m; lpk = fmaxf(lpk, m);
        if (m > 0.0f) { float inv = 1.0f / m; lur += re * inv; lui += im * inv; }
        else          { lur += 1.0f; }
        const float* w1 = Wc + t * K_;            // phase @ f=t
        const float* w2 = Wc + (257 + t) * K_;    // mag   @ f=257+t
        const float* w3 = Wc + (513 + t) * K_;    // bicoh @ f=513+t
        #pragma unroll
        for (int k = 0; k < K_; k++) {
            acc[k] += ph * w1[k] + m * w2[k];
            sb[k]  += m * w3[k];
        }
    }
    float sm  = bsum(lsm, red);
    float sm2 = bsum(lsm2, red);
    float sfm = bsum(lsfm, red);
    float pk  = bmax(lpk, red);
    float sur = bsum(lur, red);
    float sui = bsum(lui, red);

    // ---- inclusive scan of mag (Hillis-Steele, ping-pong cs<->fr) ----
    cs[t0] = mg[t0]; cs[t1] = mg[t1];
    __syncthreads();
    {
        float* src = cs; float* dst = fr;
        for (int d = 1; d < 256; d <<= 1) {
            #pragma unroll
            for (int e = 0; e < 2; e++) {
                int t = tid + e * 128;
                float v = src[t];
                if (t >= d) v += src[t - d];
                dst[t] = v;
            }
            __syncthreads();
            float* tmp = src; src = dst; dst = tmp;
        }
        // 8 iterations (even) -> result back in cs
    }
    float total = cs[255];
    float thr1 = 0.85f * total;
    float thr2 = 0.5f  * total;
    int cand1 = 1024, cand2 = 1024;
    #pragma unroll
    for (int e = 0; e < 2; e++) {
        int t = tid + e * 128;
        float v = cs[t];
        if (v >= thr1) cand1 = min(cand1, t);
        if (v >= thr2) cand2 = min(cand2, t);
    }
    int rolli = bminI(cand1, redi);
    int medi  = bminI(cand2, redi);

    // ---- FFT #2: Hann-windowed, mean-removed (rfft -> psd) ----
    float wv0 = (xv0 - mean) * (0.5f - 0.5f * cospif((float)t0 * (1.0f / 128.0f)));
    float wv1 = (xv1 - mean) * (0.5f - 0.5f * cospif((float)t1 * (1.0f / 128.0f)));
    fr[r0] = wv0; fi[r0] = 0.0f;
    fr[r1] = wv1; fi[r1] = 0.0f;
    __syncthreads();
    fft256(fr, fi, twr, twi);
    {
        // psd bins 0..128 (f = 773+j); bins 1..127 doubled; scale = 1/(fs*sum(win^2)) = 1/24576
        int j = tid;
        float re = fr[j], im = fi[j];
        float p = (re * re + im * im) * (1.0f / 24576.0f);
        if (j != 0) p *= 2.0f;
        const float* wj = Wc + (773 + j) * K_;
        #pragma unroll
        for (int k = 0; k < K_; k++) acc[k] += p * wj[k];
        if (tid == 0) {
            float re2 = fr[128], im2 = fi[128];
            float p2 = (re2 * re2 + im2 * im2) * (1.0f / 24576.0f);  // Nyquist not doubled
            const float* w8 = Wc + (773 + 128) * K_;
            #pragma unroll
            for (int k = 0; k < K_; k++) acc[k] += p2 * w8[k];
        }
    }
    __syncthreads();   // psd reads done before overwriting fr/fi

    // ---- FFT #3: analytic signal envelope. z = ifft(X*h); |z| = |fft(conj(X*h))|/256 ----
    #pragma unroll
    for (int e = 0; e < 2; e++) {
        int t = tid + e * 128;
        int r = __brev(t) >> 24;
        float h = (t == 0 || t == 128) ? 1.0f : ((t < 128) ? 2.0f : 0.0f);
        fr[r] =  sr[t] * h;
        fi[r] = -si[t] * h;
    }
    __syncthreads();
    fft256(fr, fi, twr, twi);
    float la = 0, la2 = 0;
    #pragma unroll
    for (int e = 0; e < 2; e++) {
        int t = tid + e * 128;
        float ar = fr[t], ai = fi[t];
        float a = sqrtf(ar * ar + ai * ai) * (1.0f / 256.0f);
        la += a; la2 += a * a;
    }
    float sa  = bsum(la, red);
    float sa2 = bsum(la2, red);

    // ---- finalize scalar features & fold bicoh normalization ----
    float invn = rsqrtf(sm2);
    #pragma unroll
    for (int k = 0; k < K_; k++) acc[k] += invn * sb[k];

    if (tid == 0) {
        float pc   = sqrtf(sur * sur + sui * sui) * (1.0f / 256.0f);
        float cen  = sfm / sm;
        float rol  = (float)rolli;
        float avg  = sm * (1.0f / 256.0f);
        float medf = (medi < 128) ? (float)medi : (float)(medi - 256);
        float ma   = sa * (1.0f / 256.0f);
        float amp  = sqrtf(fmaxf(sa2 * (1.0f / 256.0f) - ma * ma, 0.0f));
        #pragma unroll
        for (int k = 0; k < K_; k++) {
            acc[k] += pc   * Wc[256 * K_ + k]
                    + cen  * Wc[769 * K_ + k]
                    + rol  * Wc[770 * K_ + k]
                    + pk   * Wc[771 * K_ + k]
                    + avg  * Wc[772 * K_ + k]
                    + medf * Wc[902 * K_ + k]
                    + amp  * Wc[903 * K_ + k];
        }
    }

    // ---- block-reduce the 5 accumulators, write partials ----
    #pragma unroll
    for (int k = 0; k < K_; k++) {
        float v = bsum(acc[k], red);
        if (tid == 0) g_part[(b * C_ + c) * K_ + k] = v;
    }
}

// ---------------------------------------------------------------------------
// Kernel 4: reduce partials over channels + bias
// ---------------------------------------------------------------------------
__global__ void reduceK(const float* __restrict__ bias, float* __restrict__ out) {
    int idx = blockIdx.x * blockDim.x + threadIdx.x;
    if (idx >= B_ * K_) return;
    int b = idx / K_;
    int k = idx - b * K_;
    float s = bias[k];
    #pragma unroll 8
    for (int c = 0; c < C_; c++) s += g_part[(b * C_ + c) * K_ + k];
    out[idx] = s;
}

// ---------------------------------------------------------------------------
extern "C" void kernel_launch(void* const* d_in, const int* in_sizes, int n_in,
                              void* d_out, int out_size) {
    const float* x    = (const float*)d_in[0];   // (1024,256,64)
    // d_in[1] = x_mark_enc, unused
    const float* W    = (const float*)d_in[2];   // (5, 57856)
    const float* bias = (const float*)d_in[3];   // (5,)
    float* out = (float*)d_out;                  // (1024,5)

    transposeW<<<(K_ * F_ * C_ + 255) / 256, 256>>>(W);
    transposeX<<<dim3(T_ / 32, C_ / 32, B_), dim3(32, 8)>>>(x);
    mainK<<<dim3(C_, B_), 128>>>();
    reduceK<<<(B_ * K_ + 255) / 256, 256>>>(bias, out);
}

// round 2
// speedup vs baseline: 2.9672x; 2.9672x over previous
#include <cuda_runtime.h>
#include <cuda_bf16.h>
#include <math.h>

// Fixed problem shapes
#define B_  1024
#define T_  256
#define C_  64
#define F_  904      // 3*256 + 129 + 7
#define K_  5
#define FC_ (F_ * C_)

// Scratch (device globals: allocation-free contract)
__device__ float g_xT[B_ * C_ * T_];          // x transposed to [b][c][t]
__device__ float g_W4[C_ * 8 * 20 * 32];      // scrambled weights [c][j][q=r*5+k][lane]
__device__ float g_part[C_ * B_ * K_];        // per-(c,b) partial dot products

// ---------------------------------------------------------------------------
// Kernel 1: build scrambled weight table.
// FFT output mapping: register j, lane l hold X[t], t = br3(j) + 8*br5(l).
// Rows: r=0 phase weights, r=1 mag, r=2 bicoh, r=3 psd (doubling+scale folded,
// zero for t>128). Layout index = ((c*8+j)*20+q)*32+l  (coalesced in lane).
// ---------------------------------------------------------------------------
__global__ void buildW4(const float* __restrict__ W) {
    int idx = blockIdx.x * blockDim.x + threadIdx.x;
    const int N = C_ * 8 * 20 * 32;
    if (idx >= N) return;
    int l  = idx & 31;
    int r1 = idx >> 5;
    int q  = r1 % 20; r1 /= 20;
    int j  = r1 & 7;
    int c  = r1 >> 3;
    const int br3[8] = {0, 4, 2, 6, 1, 5, 3, 7};
    int t = br3[j] + 8 * (int)(__brev((unsigned)l) >> 27);
    int r = q / 5, k = q - 5 * r;
    float w = 0.0f;
    if (r == 0)      w = W[k * FC_ + t * C_ + c];
    else if (r == 1) w = W[k * FC_ + (257 + t) * C_ + c];
    else if (r == 2) w = W[k * FC_ + (513 + t) * C_ + c];
    else {
        const float sc = 1.0f / 24576.0f;   // 1/(fs*sum(win^2))
        if (t == 0)        w = W[k * FC_ + 773 * C_ + c] * sc;
        else if (t < 128)  w = W[k * FC_ + (773 + t) * C_ + c] * (2.0f * sc);
        else if (t == 128) w = W[k * FC_ + (773 + 128) * C_ + c] * sc;
        // t > 128: 0 (not part of rfft psd)
    }
    g_W4[idx] = w;
}

// ---------------------------------------------------------------------------
// Kernel 2: transpose x (B,T,C) -> xT (B,C,T), 32x32 smem tiles
// ---------------------------------------------------------------------------
__global__ void transposeX(const float* __restrict__ x) {
    __shared__ float tile[32][33];
    int b  = blockIdx.z;
    int t0 = blockIdx.x * 32;
    int c0 = blockIdx.y * 32;
    int tx = threadIdx.x, ty = threadIdx.y;   // (32,8)
    #pragma unroll
    for (int i = 0; i < 32; i += 8) {
        int t = t0 + ty + i, c = c0 + tx;
        tile[ty + i][tx] = x[(b * T_ + t) * C_ + c];
    }
    __syncthreads();
    #pragma unroll
    for (int i = 0; i < 32; i += 8) {
        int c = c0 + ty + i, t = t0 + tx;
        g_xT[(b * C_ + c) * T_ + t] = tile[tx][ty + i];
    }
}

// ---------------------------------------------------------------------------
// Warp reduction helpers
// ---------------------------------------------------------------------------
__device__ __forceinline__ float wsum(float v) {
    #pragma unroll
    for (int o = 16; o > 0; o >>= 1) v += __shfl_xor_sync(0xffffffffu, v, o);
    return v;
}
__device__ __forceinline__ float wmax(float v) {
    #pragma unroll
    for (int o = 16; o > 0; o >>= 1) v = fmaxf(v, __shfl_xor_sync(0xffffffffu, v, o));
    return v;
}
__device__ __forceinline__ int wminI(int v) {
    #pragma unroll
    for (int o = 16; o > 0; o >>= 1) v = min(v, __shfl_xor_sync(0xffffffffu, v, o));
    return v;
}

// ---------------------------------------------------------------------------
// Warp FFT-256: 32 lanes x 8 complex points. Input: reg j = x[lane + 32*j]
// (natural time order). Output: reg j, lane l = X[br3(j) + 8*br5(l)].
// Steps: 8-pt DIF over regs -> twiddle W256^(lane*k2) -> 32-pt DIF over lanes.
// ---------------------------------------------------------------------------
__device__ __forceinline__ void fft256w(float ar[8], float ai[8],
                                        const float tw2r[8], const float tw2i[8],
                                        const float tw5r[4], const float tw5i[4],
                                        int lane) {
    const float Cq = 0.70710678118654752440f;
    // ---- 8-pt DIF over registers ----
    // stage d=4 with W8^j on upper outputs
    {
        float ur, ui, dr, di;
        ur = ar[0]; ui = ai[0]; dr = ur - ar[4]; di = ui - ai[4];
        ar[0] = ur + ar[4]; ai[0] = ui + ai[4];
        ar[4] = dr;         ai[4] = di;                              // W8^0 = 1
        ur = ar[1]; ui = ai[1]; dr = ur - ar[5]; di = ui - ai[5];
        ar[1] = ur + ar[5]; ai[1] = ui + ai[5];
        ar[5] = Cq * (dr + di); ai[5] = Cq * (di - dr);              // W8^1 = (C,-C)
        ur = ar[2]; ui = ai[2]; dr = ur - ar[6]; di = ui - ai[6];
        ar[2] = ur + ar[6]; ai[2] = ui + ai[6];
        ar[6] = di;         ai[6] = -dr;                             // W8^2 = -i
        ur = ar[3]; ui = ai[3]; dr = ur - ar[7]; di = ui - ai[7];
        ar[3] = ur + ar[7]; ai[3] = ui + ai[7];
        ar[7] = Cq * (di - dr); ai[7] = -Cq * (dr + di);             // W8^3 = (-C,-C)
    }
    // stage d=2 (two 4-pt DIFs), W4^1 = -i on odd upper
    #pragma unroll
    for (int base = 0; base < 8; base += 4) {
        float ur, ui, dr, di;
        ur = ar[base]; ui = ai[base];
        ar[base]     = ur + ar[base + 2]; ai[base]     = ui + ai[base + 2];
        ar[base + 2] = ur - ar[base + 2]; ai[base + 2] = ui - ai[base + 2];
        ur = ar[base + 1]; ui = ai[base + 1];
        dr = ur - ar[base + 3]; di = ui - ai[base + 3];
        ar[base + 1] = ur + ar[base + 3]; ai[base + 1] = ui + ai[base + 3];
        ar[base + 3] = di; ai[base + 3] = -dr;                        // * -i
    }
    // stage d=1
    #pragma unroll
    for (int base = 0; base < 8; base += 2) {
        float ur = ar[base], ui = ai[base];
        ar[base]     = ur + ar[base + 1]; ai[base]     = ui + ai[base + 1];
        ar[base + 1] = ur - ar[base + 1]; ai[base + 1] = ui - ai[base + 1];
    }
    // ---- twiddle W256^(lane * k2), k2 = br3(j) (baked into tw2 index) ----
    #pragma unroll
    for (int j = 0; j < 8; j++) {
        float xr = ar[j], xi = ai[j];
        ar[j] = xr * tw2r[j] - xi * tw2i[j];
        ai[j] = xr * tw2i[j] + xi * tw2r[j];
    }
    // ---- 32-pt DIF across lanes (5 stages, last has unit twiddle) ----
    #pragma unroll
    for (int j = 0; j < 8; j++) {
        float vr = ar[j], vi = ai[j];
        #pragma unroll
        for (int s = 0; s < 4; s++) {
            int m = 16 >> s;
            float pr = __shfl_xor_sync(0xffffffffu, vr, m);
            float pi = __shfl_xor_sync(0xffffffffu, vi, m);
            if (lane & m) {
                float dr = pr - vr, di = pi - vi;
                vr = dr * tw5r[s] - di * tw5i[s];
                vi = dr * tw5i[s] + di * tw5r[s];
            } else { vr += pr; vi += pi; }
        }
        float pr = __shfl_xor_sync(0xffffffffu, vr, 1);
        float pi = __shfl_xor_sync(0xffffffffu, vi, 1);
        if (lane & 1) { vr = pr - vr; vi = pi - vi; }
        else          { vr += pr;     vi += pi;     }
        ar[j] = vr; ai[j] = vi;
    }
}

// Padded smem index: conflict-free for bit-rev scatter, ordered scan read,
// and natural-order re-read (verified: t + (t>>5) maps stride-8 lane sets to
// distinct banks).
__device__ __forceinline__ int spad(int t) { return t + (t >> 5); }

// ---------------------------------------------------------------------------
// Kernel 3: main — one WARP per (b,c) task; block = 8 warps, fixed c,
// each warp loops over 8 b values. Zero __syncthreads.
// ---------------------------------------------------------------------------
__global__ void __launch_bounds__(256, 2) mainK(const float* __restrict__ W) {
    __shared__ float s_r[8][264];
    __shared__ float s_i[8][264];

    const int lane = threadIdx.x & 31;
    const int wrp  = threadIdx.x >> 5;
    const int c    = blockIdx.x;
    const int br3[8] = {0, 4, 2, 6, 1, 5, 3, 7};
    const int tbase = 8 * (int)(__brev((unsigned)lane) >> 27);

    // Per-thread twiddles (computed once, reused for 3 FFTs x 8 tasks)
    float tw2r[8], tw2i[8];
    #pragma unroll
    for (int p = 0; p < 8; p++) {
        float sv, cv;
        sincosf(-6.28318530717958647692f * (float)(lane * br3[p]) * (1.0f / 256.0f), &sv, &cv);
        tw2r[p] = cv; tw2i[p] = sv;
    }
    float tw5r[4], tw5i[4];
    #pragma unroll
    for (int s = 0; s < 4; s++) {
        int m = 16 >> s;
        float sv, cv;
        sincosf(-3.14159265358979323846f * (float)(lane & (m - 1)) / (float)m, &sv, &cv);
        tw5r[s] = cv; tw5i[s] = sv;
    }

    float* sxr = s_r[wrp];
    float* sxi = s_i[wrp];
    const float* __restrict__ Wq = g_W4 + (c * 8) * 20 * 32 + lane;

    for (int it = 0; it < 8; ++it) {
        const int b = blockIdx.y * 64 + wrp * 8 + it;
        const float* __restrict__ xin = g_xT + (b * C_ + c) * T_;

        float xv[8];
        float ssum = 0.0f;
        #pragma unroll
        for (int j = 0; j < 8; j++) { xv[j] = xin[lane + 32 * j]; ssum += xv[j]; }
        const float mean = wsum(ssum) * (1.0f / 256.0f);

        // ---- FFT #1: full spectrum ----
        float ar[8], ai[8];
        #pragma unroll
        for (int j = 0; j < 8; j++) { ar[j] = xv[j]; ai[j] = 0.0f; }
        fft256w(ar, ai, tw2r, tw2i, tw5r, tw5i, lane);

        float acc[K_] = {0, 0, 0, 0, 0};
        float sb[K_]  = {0, 0, 0, 0, 0};
        float lsm = 0, lsm2 = 0, lsfm = 0, lpk = 0, lur = 0, lui = 0;
        #pragma unroll
        for (int j = 0; j < 8; j++) {
            float re = ar[j], im = ai[j];
            int t = tbase + br3[j];
            sxr[spad(t)] = re; sxi[spad(t)] = im;
            float m2 = re * re + im * im;
            float m  = sqrtf(m2);
            float ph = atan2f(im, re);
            float fq = (t < 128) ? (float)t : (float)(t - 256);
            lsm += m; lsm2 += m2; lsfm += fq * m; lpk = fmaxf(lpk, m);
            if (m > 0.0f) { float inv = 1.0f / m; lur += re * inv; lui += im * inv; }
            else          { lur += 1.0f; }
            const float* wp = Wq + j * (20 * 32);
            #pragma unroll
            for (int k = 0; k < K_; k++) {
                acc[k] += ph * wp[k * 32] + m * wp[(5 + k) * 32];
                sb[k]  += m * wp[(10 + k) * 32];
            }
        }
        float sm  = wsum(lsm);
        float sm2 = wsum(lsm2);
        float sfm = wsum(lsfm);
        float pk  = wmax(lpk);
        float sur = wsum(lur);
        float sui = wsum(lui);

        __syncwarp();
        // ---- ordered cumsum of |X| for rolloff/median (warp scan) ----
        float cs[8];
        float run = 0.0f;
        #pragma unroll
        for (int q = 0; q < 8; q++) {
            int t = 8 * lane + q;
            float rr = sxr[spad(t)], ii = sxi[spad(t)];
            run += sqrtf(rr * rr + ii * ii);
            cs[q] = run;
        }
        float incl = run;
        #pragma unroll
        for (int o = 1; o < 32; o <<= 1) {
            float vv = __shfl_up_sync(0xffffffffu, incl, o);
            if (lane >= o) incl += vv;
        }
        float excl  = incl - run;
        float total = __shfl_sync(0xffffffffu, incl, 31);
        float thr1 = 0.85f * total, thr2 = 0.5f * total;
        int cand1 = 1 << 30, cand2 = 1 << 30;
        #pragma unroll
        for (int q = 7; q >= 0; q--) {
            float v = excl + cs[q];
            if (v >= thr1) cand1 = 8 * lane + q;
            if (v >= thr2) cand2 = 8 * lane + q;
        }
        int rolli = wminI(cand1);
        int medi  = wminI(cand2);

        // ---- FFT #2: Hann-windowed, mean-removed -> PSD dot ----
        #pragma unroll
        for (int j = 0; j < 8; j++) {
            int n = lane + 32 * j;
            float win = 0.5f - 0.5f * cospif((float)n * (1.0f / 128.0f));
            ar[j] = (xv[j] - mean) * win;
            ai[j] = 0.0f;
        }
        fft256w(ar, ai, tw2r, tw2i, tw5r, tw5i, lane);
        #pragma unroll
        for (int j = 0; j < 8; j++) {
            float p = ar[j] * ar[j] + ai[j] * ai[j];
            const float* wp = Wq + (j * 20 + 15) * 32;
            #pragma unroll
            for (int k = 0; k < K_; k++) acc[k] += p * wp[k * 32];
        }

        // ---- FFT #3: analytic envelope. |ifft(X*h)| = |fft(conj(X*h))|/256 ----
        #pragma unroll
        for (int j = 0; j < 8; j++) {
            int n = lane + 32 * j;
            float h = (n == 0 || n == 128) ? 1.0f : ((n < 128) ? 2.0f : 0.0f);
            ar[j] =  sxr[spad(n)] * h;
            ai[j] = -sxi[spad(n)] * h;
        }
        __syncwarp();   // smem reads done before next iteration's scatter
        fft256w(ar, ai, tw2r, tw2i, tw5r, tw5i, lane);
        float la = 0, la2 = 0;
        #pragma unroll
        for (int j = 0; j < 8; j++) {
            float a2 = (ar[j] * ar[j] + ai[j] * ai[j]) * (1.0f / 65536.0f);
            la += sqrtf(a2); la2 += a2;
        }
        float sa  = wsum(la);
        float sa2 = wsum(la2);

        // ---- fold bicoh normalization, reduce accumulators ----
        float invn = rsqrtf(sm2);
        #pragma unroll
        for (int k = 0; k < K_; k++) acc[k] = wsum(acc[k] + invn * sb[k]);

        if (lane == 0) {
            float pc   = sqrtf(sur * sur + sui * sui) * (1.0f / 256.0f);
            float cen  = sfm / sm;
            float rol  = (float)rolli;
            float avg  = sm * (1.0f / 256.0f);
            float medf = (medi < 128) ? (float)medi : (float)(medi - 256);
            float ma   = sa * (1.0f / 256.0f);
            float amp  = sqrtf(fmaxf(sa2 * (1.0f / 256.0f) - ma * ma, 0.0f));
            #pragma unroll
            for (int k = 0; k < K_; k++) {
                float v = acc[k]
                        + pc   * W[k * FC_ + 256 * C_ + c]
                        + cen  * W[k * FC_ + 769 * C_ + c]
                        + rol  * W[k * FC_ + 770 * C_ + c]
                        + pk   * W[k * FC_ + 771 * C_ + c]
                        + avg  * W[k * FC_ + 772 * C_ + c]
                        + medf * W[k * FC_ + 902 * C_ + c]
                        + amp  * W[k * FC_ + 903 * C_ + c];
                g_part[(c * B_ + b) * K_ + k] = v;
            }
        }
    }
}

// ---------------------------------------------------------------------------
// Kernel 4: reduce partials over channels + bias (coalesced layout [c][b][k])
// ---------------------------------------------------------------------------
__global__ void reduceK(const float* __restrict__ bias, float* __restrict__ out) {
    int idx = blockIdx.x * blockDim.x + threadIdx.x;
    if (idx >= B_ * K_) return;
    int b = idx / K_;
    int k = idx - b * K_;
    float s = bias[k];
    #pragma unroll 8
    for (int c = 0; c < C_; c++) s += g_part[(c * B_ + b) * K_ + k];
    out[idx] = s;
}

// ---------------------------------------------------------------------------
extern "C" void kernel_launch(void* const* d_in, const int* in_sizes, int n_in,
                              void* d_out, int out_size) {
    const float* x    = (const float*)d_in[0];   // (1024,256,64)
    // d_in[1] = x_mark_enc, unused
    const float* W    = (const float*)d_in[2];   // (5, 57856)
    const float* bias = (const float*)d_in[3];   // (5,)
    float* out = (float*)d_out;                  // (1024,5)

    buildW4<<<(C_ * 8 * 20 * 32 + 255) / 256, 256>>>(W);
    transposeX<<<dim3(T_ / 32, C_ / 32, B_), dim3(32, 8)>>>(x);
    mainK<<<dim3(C_, 16), 256>>>(W);
    reduceK<<<(B_ * K_ + 255) / 256, 256>>>(bias, out);
}

// round 5
// speedup vs baseline: 3.1348x; 1.0565x over previous
#include <cuda_runtime.h>
#include <cuda_bf16.h>
#include <math.h>

// Fixed problem shapes
#define B_  1024
#define T_  256
#define C_  64
#define F_  904      // 3*256 + 129 + 7
#define K_  5
#define FC_ (F_ * C_)

// Scratch (device globals: allocation-free contract)
__device__ float g_xT[B_ * C_ * T_];          // x transposed to [b][c][t]
__device__ float g_W4[C_ * 8 * 20 * 32];      // scrambled weights [c][j][q=r*5+k][lane]
__device__ float g_part[C_ * B_ * K_];        // per-(c,b) partial dot products

// ---------------------------------------------------------------------------
// Kernel 1: build scrambled weight table.
// FFT output mapping: register j, lane l hold X[t], t = br3(j) + 8*br5(l).
// Rows: r=0 phase, r=1 mag, r=2 bicoh, r=3 psd (doubling+scale folded, zero
// for t>128). Layout index = ((c*8+j)*20+q)*32+l (coalesced in lane).
// ---------------------------------------------------------------------------
__global__ void buildW4(const float* __restrict__ W) {
    int idx = blockIdx.x * blockDim.x + threadIdx.x;
    const int N = C_ * 8 * 20 * 32;
    if (idx >= N) return;
    int l  = idx & 31;
    int r1 = idx >> 5;
    int q  = r1 % 20; r1 /= 20;
    int j  = r1 & 7;
    int c  = r1 >> 3;
    const int br3[8] = {0, 4, 2, 6, 1, 5, 3, 7};
    int t = br3[j] + 8 * (int)(__brev((unsigned)l) >> 27);
    int r = q / 5, k = q - 5 * r;
    float w = 0.0f;
    if (r == 0)      w = W[k * FC_ + t * C_ + c];
    else if (r == 1) w = W[k * FC_ + (257 + t) * C_ + c];
    else if (r == 2) w = W[k * FC_ + (513 + t) * C_ + c];
    else {
        const float sc = 1.0f / 24576.0f;   // 1/(fs*sum(win^2))
        if (t == 0)        w = W[k * FC_ + 773 * C_ + c] * sc;
        else if (t < 128)  w = W[k * FC_ + (773 + t) * C_ + c] * (2.0f * sc);
        else if (t == 128) w = W[k * FC_ + (773 + 128) * C_ + c] * sc;
    }
    g_W4[idx] = w;
}

// ---------------------------------------------------------------------------
// Kernel 2: transpose x (B,T,C) -> xT (B,C,T)
// ---------------------------------------------------------------------------
__global__ void transposeX(const float* __restrict__ x) {
    __shared__ float tile[32][33];
    int b  = blockIdx.z;
    int t0 = blockIdx.x * 32;
    int c0 = blockIdx.y * 32;
    int tx = threadIdx.x, ty = threadIdx.y;   // (32,8)
    #pragma unroll
    for (int i = 0; i < 32; i += 8) {
        int t = t0 + ty + i, c = c0 + tx;
        tile[ty + i][tx] = x[(b * T_ + t) * C_ + c];
    }
    __syncthreads();
    #pragma unroll
    for (int i = 0; i < 32; i += 8) {
        int c = c0 + ty + i, t = t0 + tx;
        g_xT[(b * C_ + c) * T_ + t] = tile[tx][ty + i];
    }
}

// ---------------------------------------------------------------------------
// Warp reduction helpers
// ---------------------------------------------------------------------------
__device__ __forceinline__ float wsum(float v) {
    #pragma unroll
    for (int o = 16; o > 0; o >>= 1) v += __shfl_xor_sync(0xffffffffu, v, o);
    return v;
}
__device__ __forceinline__ float wmax(float v) {
    #pragma unroll
    for (int o = 16; o > 0; o >>= 1) v = fmaxf(v, __shfl_xor_sync(0xffffffffu, v, o));
    return v;
}
__device__ __forceinline__ int wminI(int v) {
    #pragma unroll
    for (int o = 16; o > 0; o >>= 1) v = min(v, __shfl_xor_sync(0xffffffffu, v, o));
    return v;
}

// ---------------------------------------------------------------------------
// Fast atan2 (max err ~1e-6 rad), branch-free selects.
// ---------------------------------------------------------------------------
__device__ __forceinline__ float fatan2f(float y, float x) {
    float ax = fabsf(x), ay = fabsf(y);
    float mx = fmaxf(ax, ay), mn = fminf(ax, ay);
    float a = __fdividef(mn, mx);
    if (mx == 0.0f) a = 0.0f;
    float s = a * a;
    float p =            -0.0040540580f;
    p = fmaf(p, s,        0.0218612288f);
    p = fmaf(p, s,       -0.0559098861f);
    p = fmaf(p, s,        0.0964200441f);
    p = fmaf(p, s,       -0.1390853351f);
    p = fmaf(p, s,        0.1994653599f);
    p = fmaf(p, s,       -0.3332985605f);
    p = fmaf(p, s,        0.9999993329f);
    float r = p * a;
    if (ay > ax)  r = 1.57079632679489662f - r;
    if (x < 0.0f) r = 3.14159265358979324f - r;
    return copysignf(r, y);
}

// ---------------------------------------------------------------------------
// Warp FFT-256: 32 lanes x 8 complex points. Input: reg j = z[lane + 32*j].
// Output: reg j, lane l = Z[br3(j) + 8*br5(l)].
// ---------------------------------------------------------------------------
__device__ __forceinline__ void fft256w(float ar[8], float ai[8],
                                        const float tw2r[8], const float tw2i[8],
                                        const float tw5r[4], const float tw5i[4],
                                        int lane) {
    const float Cq = 0.70710678118654752440f;
    {   // stage d=4 with W8^j
        float ur, ui, dr, di;
        ur = ar[0]; ui = ai[0]; dr = ur - ar[4]; di = ui - ai[4];
        ar[0] = ur + ar[4]; ai[0] = ui + ai[4];
        ar[4] = dr;         ai[4] = di;
        ur = ar[1]; ui = ai[1]; dr = ur - ar[5]; di = ui - ai[5];
        ar[1] = ur + ar[5]; ai[1] = ui + ai[5];
        ar[5] = Cq * (dr + di); ai[5] = Cq * (di - dr);
        ur = ar[2]; ui = ai[2]; dr = ur - ar[6]; di = ui - ai[6];
        ar[2] = ur + ar[6]; ai[2] = ui + ai[6];
        ar[6] = di;         ai[6] = -dr;
        ur = ar[3]; ui = ai[3]; dr = ur - ar[7]; di = ui - ai[7];
        ar[3] = ur + ar[7]; ai[3] = ui + ai[7];
        ar[7] = Cq * (di - dr); ai[7] = -Cq * (dr + di);
    }
    #pragma unroll
    for (int base = 0; base < 8; base += 4) {   // stage d=2
        float ur, ui, dr, di;
        ur = ar[base]; ui = ai[base];
        ar[base]     = ur + ar[base + 2]; ai[base]     = ui + ai[base + 2];
        ar[base + 2] = ur - ar[base + 2]; ai[base + 2] = ui - ai[base + 2];
        ur = ar[base + 1]; ui = ai[base + 1];
        dr = ur - ar[base + 3]; di = ui - ai[base + 3];
        ar[base + 1] = ur + ar[base + 3]; ai[base + 1] = ui + ai[base + 3];
        ar[base + 3] = di; ai[base + 3] = -dr;
    }
    #pragma unroll
    for (int base = 0; base < 8; base += 2) {   // stage d=1
        float ur = ar[base], ui = ai[base];
        ar[base]     = ur + ar[base + 1]; ai[base]     = ui + ai[base + 1];
        ar[base + 1] = ur - ar[base + 1]; ai[base + 1] = ui - ai[base + 1];
    }
    #pragma unroll
    for (int j = 0; j < 8; j++) {               // twiddle W256^(lane*br3(j))
        float xr = ar[j], xi = ai[j];
        ar[j] = xr * tw2r[j] - xi * tw2i[j];
        ai[j] = xr * tw2i[j] + xi * tw2r[j];
    }
    #pragma unroll
    for (int j = 0; j < 8; j++) {               // 32-pt DIF across lanes
        float vr = ar[j], vi = ai[j];
        #pragma unroll
        for (int s = 0; s < 4; s++) {
            int m = 16 >> s;
            float pr = __shfl_xor_sync(0xffffffffu, vr, m);
            float pi = __shfl_xor_sync(0xffffffffu, vi, m);
            if (lane & m) {
                float dr = pr - vr, di = pi - vi;
                vr = dr * tw5r[s] - di * tw5i[s];
                vi = dr * tw5i[s] + di * tw5r[s];
            } else { vr += pr; vi += pi; }
        }
        float pr = __shfl_xor_sync(0xffffffffu, vr, 1);
        float pi = __shfl_xor_sync(0xffffffffu, vi, 1);
        if (lane & 1) { vr = pr - vr; vi = pi - vi; }
        else          { vr += pr;     vi += pi;     }
        ar[j] = vr; ai[j] = vi;
    }
}

// Padded smem index: conflict-free for bit-rev scatter, stride-8 mirrored
// reads, ordered scan reads, and natural-order reads.
__device__ __forceinline__ int spad(int t) { return t + (t >> 5); }

// ---------------------------------------------------------------------------
// Kernel 3: main — one WARP per (b,c) task; block = 4 warps, fixed c,
// each warp loops over 8 b values. Packed FFT: z = x + i*(x-mean)*win.
// ---------------------------------------------------------------------------
__global__ void __launch_bounds__(128, 4) mainK(const float* __restrict__ W) {
    __shared__ float s_zr[4][264];
    __shared__ float s_zi[4][264];
    __shared__ float s_m [4][264];

    const int lane = threadIdx.x & 31;
    const int wrp  = threadIdx.x >> 5;
    const int c    = blockIdx.x;
    const int br3[8] = {0, 4, 2, 6, 1, 5, 3, 7};
    const int tbase = 8 * (int)(__brev((unsigned)lane) >> 27);

    // Per-thread twiddles + Hann window (hoisted; reused across 8 tasks)
    float tw2r[8], tw2i[8], win[8];
    #pragma unroll
    for (int p = 0; p < 8; p++) {
        float sv, cv;
        sincosf(-6.28318530717958647692f * (float)(lane * br3[p]) * (1.0f / 256.0f), &sv, &cv);
        tw2r[p] = cv; tw2i[p] = sv;
        win[p] = 0.5f - 0.5f * cospif((float)(lane + 32 * p) * (1.0f / 128.0f));
    }
    float tw5r[4], tw5i[4];
    #pragma unroll
    for (int s = 0; s < 4; s++) {
        int m = 16 >> s;
        float sv, cv;
        sincosf(-3.14159265358979323846f * (float)(lane & (m - 1)) / (float)m, &sv, &cv);
        tw5r[s] = cv; tw5i[s] = sv;
    }

    float* szr = s_zr[wrp];
    float* szi = s_zi[wrp];
    float* smg = s_m [wrp];
    const float* __restrict__ Wq = g_W4 + (c * 8) * 20 * 32 + lane;

    for (int it = 0; it < 8; ++it) {
        const int b = blockIdx.y * 32 + wrp * 8 + it;
        const float* __restrict__ xin = g_xT + (b * C_ + c) * T_;

        float xv[8];
        float ssum = 0.0f;
        #pragma unroll
        for (int j = 0; j < 8; j++) { xv[j] = xin[lane + 32 * j]; ssum += xv[j]; }
        const float mean = wsum(ssum) * (1.0f / 256.0f);

        // ---- packed FFT: real = x, imag = (x-mean)*win ----
        float ar[8], ai[8];
        #pragma unroll
        for (int j = 0; j < 8; j++) { ar[j] = xv[j]; ai[j] = (xv[j] - mean) * win[j]; }
        fft256w(ar, ai, tw2r, tw2i, tw5r, tw5i, lane);

        // scatter Z to smem (needed for mirror unpack + Hilbert rebuild)
        #pragma unroll
        for (int j = 0; j < 8; j++) {
            int t = tbase + br3[j];
            szr[spad(t)] = ar[j]; szi[spad(t)] = ai[j];
        }
        __syncwarp();

        // ---- unpack + per-bin features + fused dot ----
        float acc[K_] = {0, 0, 0, 0, 0};
        float sb[K_]  = {0, 0, 0, 0, 0};
        float lsm = 0, lsm2 = 0, lsfm = 0, lpk = 0, lur = 0, lui = 0;
        #pragma unroll
        for (int j = 0; j < 8; j++) {
            int t = tbase + br3[j];
            int mt = (256 - t) & 255;
            float Mr = szr[spad(mt)], Mi = szi[spad(mt)];
            float Xr = 0.5f * (ar[j] + Mr);
            float Xi = 0.5f * (ai[j] - Mi);
            float Wr = 0.5f * (ai[j] + Mi);
            float Wi = 0.5f * (Mr - ar[j]);
            float m2 = Xr * Xr + Xi * Xi;
            float rs = (m2 > 0.0f) ? rsqrtf(m2) : 0.0f;
            float m  = m2 * rs;
            smg[spad(t)] = m;
            float ph = fatan2f(Xi, Xr);
            float p  = Wr * Wr + Wi * Wi;   // psd (scale folded in weights)
            float fq = (t < 128) ? (float)t : (float)(t - 256);
            lsm += m; lsm2 += m2; lsfm += fq * m; lpk = fmaxf(lpk, m);
            if (m2 > 0.0f) { lur += Xr * rs; lui += Xi * rs; }
            else           { lur += 1.0f; }
            const float* wp = Wq + j * (20 * 32);
            #pragma unroll
            for (int k = 0; k < K_; k++) {
                acc[k] += ph * wp[k * 32] + m * wp[(5 + k) * 32] + p * wp[(15 + k) * 32];
                sb[k]  += m * wp[(10 + k) * 32];
            }
        }
        float sm  = wsum(lsm);
        float sm2 = wsum(lsm2);
        float sfm = wsum(lsfm);
        float pk  = wmax(lpk);
        float sur = wsum(lur);
        float sui = wsum(lui);

        __syncwarp();
        // ---- ordered cumsum of mag for rolloff/median (warp scan) ----
        float cs[8];
        float run = 0.0f;
        #pragma unroll
        for (int q = 0; q < 8; q++) {
            run += smg[spad(8 * lane + q)];
            cs[q] = run;
        }
        float incl = run;
        #pragma unroll
        for (int o = 1; o < 32; o <<= 1) {
            float vv = __shfl_up_sync(0xffffffffu, incl, o);
            if (lane >= o) incl += vv;
        }
        float excl  = incl - run;
        float total = __shfl_sync(0xffffffffu, incl, 31);
        float thr1 = 0.85f * total, thr2 = 0.5f * total;
        int cand1 = 1 << 30, cand2 = 1 << 30;
        #pragma unroll
        for (int q = 7; q >= 0; q--) {
            float v = excl + cs[q];
            if (v >= thr1) cand1 = 8 * lane + q;
            if (v >= thr2) cand2 = 8 * lane + q;
        }
        int rolli = wminI(cand1);
        int medi  = wminI(cand2);

        // ---- Hilbert FFT: input conj(X*h) in natural order from smem Z ----
        #pragma unroll
        for (int j = 0; j < 8; j++) {
            int n = lane + 32 * j;
            int mn_ = (256 - n) & 255;
            float Zr = szr[spad(n)],   Zi = szi[spad(n)];
            float Mr = szr[spad(mn_)], Mi = szi[spad(mn_)];
            float Xr = 0.5f * (Zr + Mr);
            float Xi = 0.5f * (Zi - Mi);
            float h = (n == 0 || n == 128) ? 1.0f : ((n < 128) ? 2.0f : 0.0f);
            ar[j] =  Xr * h;
            ai[j] = -Xi * h;
        }
        __syncwarp();   // smem reads done before next iteration's scatter
        fft256w(ar, ai, tw2r, tw2i, tw5r, tw5i, lane);
        float la = 0, la2 = 0;
        #pragma unroll
        for (int j = 0; j < 8; j++) {
            float a2 = (ar[j] * ar[j] + ai[j] * ai[j]) * (1.0f / 65536.0f);
            float rs = (a2 > 0.0f) ? rsqrtf(a2) : 0.0f;
            la += a2 * rs; la2 += a2;
        }
        float sa  = wsum(la);
        float sa2 = wsum(la2);

        // ---- fold bicoh normalization, reduce accumulators ----
        float invn = rsqrtf(sm2);
        #pragma unroll
        for (int k = 0; k < K_; k++) acc[k] = wsum(acc[k] + invn * sb[k]);

        if (lane == 0) {
            float pc   = sqrtf(sur * sur + sui * sui) * (1.0f / 256.0f);
            float cen  = sfm / sm;
            float rol  = (float)rolli;
            float avg  = sm * (1.0f / 256.0f);
            float medf = (medi < 128) ? (float)medi : (float)(medi - 256);
            float ma   = sa * (1.0f / 256.0f);
            float amp  = sqrtf(fmaxf(sa2 * (1.0f / 256.0f) - ma * ma, 0.0f));
            #pragma unroll
            for (int k = 0; k < K_; k++) {
                float v = acc[k]
                        + pc   * W[k * FC_ + 256 * C_ + c]
                        + cen  * W[k * FC_ + 769 * C_ + c]
                        + rol  * W[k * FC_ + 770 * C_ + c]
                        + pk   * W[k * FC_ + 771 * C_ + c]
                        + avg  * W[k * FC_ + 772 * C_ + c]
                        + medf * W[k * FC_ + 902 * C_ + c]
                        + amp  * W[k * FC_ + 903 * C_ + c];
                g_part[(c * B_ + b) * K_ + k] = v;
            }
        }
    }
}

// ---------------------------------------------------------------------------
// Kernel 4: reduce partials over channels + bias. One block per b.
// ---------------------------------------------------------------------------
__global__ void reduceK(const float* __restrict__ bias, float* __restrict__ out) {
    __shared__ float s[320];
    int b = blockIdx.x;
    int tid = threadIdx.x;                 // 320 threads
    int c = tid / 5, k = tid - 5 * c;
    s[tid] = g_part[(c * B_ + b) * K_ + k];
    __syncthreads();
    #pragma unroll
    for (int st = 160; st >= 5; st >>= 1) {
        if (tid < st) s[tid] += s[tid + st];
        __syncthreads();
    }
    if (tid < 5) out[b * K_ + tid] = s[tid] + bias[tid];
}

// ---------------------------------------------------------------------------
extern "C" void kernel_launch(void* const* d_in, const int* in_sizes, int n_in,
                              void* d_out, int out_size) {
    const float* x    = (const float*)d_in[0];   // (1024,256,64)
    // d_in[1] = x_mark_enc, unused
    const float* W    = (const float*)d_in[2];   // (5, 57856)
    const float* bias = (const float*)d_in[3];   // (5,)
    float* out = (float*)d_out;                  // (1024,5)

    buildW4<<<(C_ * 8 * 20 * 32 + 255) / 256, 256>>>(W);
    transposeX<<<dim3(T_ / 32, C_ / 32, B_), dim3(32, 8)>>>(x);
    mainK<<<dim3(C_, 32), 128>>>(W);
    reduceK<<<B_, 320>>>(bias, out);
}

// round 6
// speedup vs baseline: 3.3803x; 1.0783x over previous
#include <cuda_runtime.h>
#include <cuda_bf16.h>
#include <math.h>

// Fixed problem shapes
#define B_  1024
#define T_  256
#define C_  64
#define F_  904      // 3*256 + 129 + 7
#define K_  5
#define FC_ (F_ * C_)

// Scratch (device globals: allocation-free contract)
__device__ float g_xT[B_ * C_ * T_];          // x transposed to [b][c][t]
__device__ float g_W4[C_ * 8 * 20 * 32];      // scrambled weights [c][j][q=r*5+k][lane]
__device__ float g_part[C_ * B_ * K_];        // per-(c,b) partial dot products

// ---------------------------------------------------------------------------
// Packed f32x2 helpers (sm_100a). Components of a float2 stay individually
// addressable registers; the asm "l" constraint makes ptxas pair them.
// f2sub is exact: fma(b, (-1,-1), a) = a - b in each half.
// ---------------------------------------------------------------------------
__device__ __forceinline__ float2 f2add(float2 a, float2 b) {
    unsigned long long ua = *reinterpret_cast<unsigned long long*>(&a);
    unsigned long long ub = *reinterpret_cast<unsigned long long*>(&b);
    unsigned long long ud;
    asm("add.rn.f32x2 %0, %1, %2;" : "=l"(ud) : "l"(ua), "l"(ub));
    return *reinterpret_cast<float2*>(&ud);
}
__device__ __forceinline__ float2 f2sub(float2 a, float2 b) {
    float2 n1 = make_float2(-1.0f, -1.0f);
    unsigned long long ua = *reinterpret_cast<unsigned long long*>(&a);
    unsigned long long ub = *reinterpret_cast<unsigned long long*>(&b);
    unsigned long long un = *reinterpret_cast<unsigned long long*>(&n1);
    unsigned long long ud;
    asm("fma.rn.f32x2 %0, %1, %2, %3;" : "=l"(ud) : "l"(ub), "l"(un), "l"(ua));
    return *reinterpret_cast<float2*>(&ud);
}

// ---------------------------------------------------------------------------
// Kernel 1: build scrambled weight table.
// FFT output mapping: register j, lane l hold X[t], t = br3(j) + 8*br5(l).
// Rows: r=0 phase, r=1 mag, r=2 bicoh, r=3 psd (doubling+scale folded, zero
// for t>128). Layout index = ((c*8+j)*20+q)*32+l (coalesced in lane).
// ---------------------------------------------------------------------------
__global__ void buildW4(const float* __restrict__ W) {
    int idx = blockIdx.x * blockDim.x + threadIdx.x;
    const int N = C_ * 8 * 20 * 32;
    if (idx >= N) return;
    int l  = idx & 31;
    int r1 = idx >> 5;
    int q  = r1 % 20; r1 /= 20;
    int j  = r1 & 7;
    int c  = r1 >> 3;
    const int br3[8] = {0, 4, 2, 6, 1, 5, 3, 7};
    int t = br3[j] + 8 * (int)(__brev((unsigned)l) >> 27);
    int r = q / 5, k = q - 5 * r;
    float w = 0.0f;
    if (r == 0)      w = W[k * FC_ + t * C_ + c];
    else if (r == 1) w = W[k * FC_ + (257 + t) * C_ + c];
    else if (r == 2) w = W[k * FC_ + (513 + t) * C_ + c];
    else {
        const float sc = 1.0f / 24576.0f;   // 1/(fs*sum(win^2))
        if (t == 0)        w = W[k * FC_ + 773 * C_ + c] * sc;
        else if (t < 128)  w = W[k * FC_ + (773 + t) * C_ + c] * (2.0f * sc);
        else if (t == 128) w = W[k * FC_ + (773 + 128) * C_ + c] * sc;
    }
    g_W4[idx] = w;
}

// ---------------------------------------------------------------------------
// Kernel 2: transpose x (B,T,C) -> xT (B,C,T)
// ---------------------------------------------------------------------------
__global__ void transposeX(const float* __restrict__ x) {
    __shared__ float tile[32][33];
    int b  = blockIdx.z;
    int t0 = blockIdx.x * 32;
    int c0 = blockIdx.y * 32;
    int tx = threadIdx.x, ty = threadIdx.y;   // (32,8)
    #pragma unroll
    for (int i = 0; i < 32; i += 8) {
        int t = t0 + ty + i, c = c0 + tx;
        tile[ty + i][tx] = x[(b * T_ + t) * C_ + c];
    }
    __syncthreads();
    #pragma unroll
    for (int i = 0; i < 32; i += 8) {
        int c = c0 + ty + i, t = t0 + tx;
        g_xT[(b * C_ + c) * T_ + t] = tile[tx][ty + i];
    }
}

// ---------------------------------------------------------------------------
// Warp reduction helpers
// ---------------------------------------------------------------------------
__device__ __forceinline__ float wsum(float v) {
    #pragma unroll
    for (int o = 16; o > 0; o >>= 1) v += __shfl_xor_sync(0xffffffffu, v, o);
    return v;
}
__device__ __forceinline__ float wmax(float v) {
    #pragma unroll
    for (int o = 16; o > 0; o >>= 1) v = fmaxf(v, __shfl_xor_sync(0xffffffffu, v, o));
    return v;
}
__device__ __forceinline__ int wminI(int v) {
    #pragma unroll
    for (int o = 16; o > 0; o >>= 1) v = min(v, __shfl_xor_sync(0xffffffffu, v, o));
    return v;
}

// ---------------------------------------------------------------------------
// Fast atan2 (max err ~1e-6 rad), branch-free selects.
// ---------------------------------------------------------------------------
__device__ __forceinline__ float fatan2f(float y, float x) {
    float ax = fabsf(x), ay = fabsf(y);
    float mx = fmaxf(ax, ay), mn = fminf(ax, ay);
    float a = __fdividef(mn, mx);
    if (mx == 0.0f) a = 0.0f;
    float s = a * a;
    float p =            -0.0040540580f;
    p = fmaf(p, s,        0.0218612288f);
    p = fmaf(p, s,       -0.0559098861f);
    p = fmaf(p, s,        0.0964200441f);
    p = fmaf(p, s,       -0.1390853351f);
    p = fmaf(p, s,        0.1994653599f);
    p = fmaf(p, s,       -0.3332985605f);
    p = fmaf(p, s,        0.9999993329f);
    float r = p * a;
    if (ay > ax)  r = 1.57079632679489662f - r;
    if (x < 0.0f) r = 3.14159265358979324f - r;
    return copysignf(r, y);
}

// ---------------------------------------------------------------------------
// Warp FFT-256 on packed float2 state: 32 lanes x 8 complex points.
// Input: z[j] = value at time n = lane + 32*j. Output: z[j], lane l =
// Z[br3(j) + 8*br5(l)]. Butterfly adds/subs use f32x2 packed ops.
// ---------------------------------------------------------------------------
__device__ __forceinline__ void fft256w(float2 z[8],
                                        const float tw2r[8], const float tw2i[8],
                                        const float tw5r[4], const float tw5i[4],
                                        int lane) {
    const float Cq = 0.70710678118654752440f;
    {   // stage d=4 with W8^j on the difference outputs
        float2 u, d;
        u = z[0]; d = f2sub(z[0], z[4]); z[0] = f2add(u, z[4]);
        z[4] = d;                                               // W8^0 = 1
        u = z[1]; d = f2sub(z[1], z[5]); z[1] = f2add(u, z[5]);
        z[5] = make_float2(Cq * (d.x + d.y), Cq * (d.y - d.x)); // W8^1
        u = z[2]; d = f2sub(z[2], z[6]); z[2] = f2add(u, z[6]);
        z[6] = make_float2(d.y, -d.x);                          // W8^2 = -i
        u = z[3]; d = f2sub(z[3], z[7]); z[3] = f2add(u, z[7]);
        z[7] = make_float2(Cq * (d.y - d.x), -Cq * (d.x + d.y));// W8^3
    }
    #pragma unroll
    for (int base = 0; base < 8; base += 4) {   // stage d=2
        float2 u, d;
        u = z[base];
        z[base]     = f2add(u, z[base + 2]);
        z[base + 2] = f2sub(u, z[base + 2]);
        u = z[base + 1];
        d = f2sub(z[base + 1], z[base + 3]);
        z[base + 1] = f2add(u, z[base + 3]);
        z[base + 3] = make_float2(d.y, -d.x);                   // * -i
    }
    #pragma unroll
    for (int base = 0; base < 8; base += 2) {   // stage d=1
        float2 u = z[base];
        z[base]     = f2add(u, z[base + 1]);
        z[base + 1] = f2sub(u, z[base + 1]);
    }
    #pragma unroll
    for (int j = 1; j < 8; j++) {               // twiddle W256^(lane*br3(j)); j=0 identity
        float xr = z[j].x, xi = z[j].y;
        z[j].x = xr * tw2r[j] - xi * tw2i[j];
        z[j].y = xr * tw2i[j] + xi * tw2r[j];
    }
    #pragma unroll
    for (int j = 0; j < 8; j++) {               // 32-pt DIF across lanes
        float2 v = z[j];
        #pragma unroll
        for (int s = 0; s < 4; s++) {
            int m = 16 >> s;
            float2 p;
            p.x = __shfl_xor_sync(0xffffffffu, v.x, m);
            p.y = __shfl_xor_sync(0xffffffffu, v.y, m);
            if (lane & m) {
                float2 d = f2sub(p, v);
                v = make_float2(d.x * tw5r[s] - d.y * tw5i[s],
                                d.x * tw5i[s] + d.y * tw5r[s]);
            } else {
                v = f2add(v, p);
            }
        }
        float2 p;
        p.x = __shfl_xor_sync(0xffffffffu, v.x, 1);
        p.y = __shfl_xor_sync(0xffffffffu, v.y, 1);
        v = (lane & 1) ? f2sub(p, v) : f2add(v, p);
        z[j] = v;
    }
}

// Padded smem index: conflict-free for bit-rev scatter, stride-8 mirrored
// reads, ordered scan reads, and natural-order reads.
__device__ __forceinline__ int spad(int t) { return t + (t >> 5); }

// ---------------------------------------------------------------------------
// Kernel 3: main — one WARP per (b,c) task; block = 4 warps, fixed c,
// each warp loops over 8 b values. Packed FFT: z = x + i*(x-mean)*win.
// ---------------------------------------------------------------------------
__global__ void __launch_bounds__(128, 4) mainK(const float* __restrict__ W) {
    __shared__ float s_zr[4][264];
    __shared__ float s_zi[4][264];
    __shared__ float s_m [4][264];

    const int lane = threadIdx.x & 31;
    const int wrp  = threadIdx.x >> 5;
    const int c    = blockIdx.x;
    const int br3[8] = {0, 4, 2, 6, 1, 5, 3, 7};
    const int tbase = 8 * (int)(__brev((unsigned)lane) >> 27);

    // Per-thread twiddles + Hann window (hoisted; reused across 8 tasks)
    float tw2r[8], tw2i[8], win[8];
    #pragma unroll
    for (int p = 0; p < 8; p++) {
        float sv, cv;
        sincosf(-6.28318530717958647692f * (float)(lane * br3[p]) * (1.0f / 256.0f), &sv, &cv);
        tw2r[p] = cv; tw2i[p] = sv;
        win[p] = 0.5f - 0.5f * cospif((float)(lane + 32 * p) * (1.0f / 128.0f));
    }
    float tw5r[4], tw5i[4];
    #pragma unroll
    for (int s = 0; s < 4; s++) {
        int m = 16 >> s;
        float sv, cv;
        sincosf(-3.14159265358979323846f * (float)(lane & (m - 1)) / (float)m, &sv, &cv);
        tw5r[s] = cv; tw5i[s] = sv;
    }

    float* szr = s_zr[wrp];
    float* szi = s_zi[wrp];
    float* smg = s_m [wrp];
    const float* __restrict__ Wq = g_W4 + (c * 8) * 20 * 32 + lane;

    for (int it = 0; it < 8; ++it) {
        const int b = blockIdx.y * 32 + wrp * 8 + it;
        const float* __restrict__ xin = g_xT + (b * C_ + c) * T_;

        float xv[8];
        float ssum = 0.0f;
        #pragma unroll
        for (int j = 0; j < 8; j++) { xv[j] = xin[lane + 32 * j]; ssum += xv[j]; }
        const float mean = wsum(ssum) * (1.0f / 256.0f);

        // ---- packed FFT: real = x, imag = (x-mean)*win ----
        float2 z[8];
        #pragma unroll
        for (int j = 0; j < 8; j++) {
            z[j].x = xv[j];
            z[j].y = (xv[j] - mean) * win[j];
        }
        fft256w(z, tw2r, tw2i, tw5r, tw5i, lane);

        // scatter Z to smem (needed for mirror unpack + Hilbert rebuild)
        #pragma unroll
        for (int j = 0; j < 8; j++) {
            int t = tbase + br3[j];
            szr[spad(t)] = z[j].x; szi[spad(t)] = z[j].y;
        }
        __syncwarp();

        // ---- unpack + per-bin features + fused dot ----
        float acc[K_] = {0, 0, 0, 0, 0};
        float sb[K_]  = {0, 0, 0, 0, 0};
        float lsm = 0, lsm2 = 0, lsfm = 0, lpk = 0, lur = 0, lui = 0;
        #pragma unroll
        for (int j = 0; j < 8; j++) {
            int t = tbase + br3[j];
            int mt = (256 - t) & 255;
            float Mr = szr[spad(mt)], Mi = szi[spad(mt)];
            float Xr = 0.5f * (z[j].x + Mr);
            float Xi = 0.5f * (z[j].y - Mi);
            float Wr = 0.5f * (z[j].y + Mi);
            float Wi = 0.5f * (Mr - z[j].x);
            float m2 = Xr * Xr + Xi * Xi;
            float rs = (m2 > 0.0f) ? rsqrtf(m2) : 0.0f;
            float m  = m2 * rs;
            smg[spad(t)] = m;
            float ph = fatan2f(Xi, Xr);
            float p  = Wr * Wr + Wi * Wi;   // psd (scale folded in weights)
            float fq = (t < 128) ? (float)t : (float)(t - 256);
            lsm += m; lsm2 += m2; lsfm += fq * m; lpk = fmaxf(lpk, m);
            if (m2 > 0.0f) { lur += Xr * rs; lui += Xi * rs; }
            else           { lur += 1.0f; }
            const float* wp = Wq + j * (20 * 32);
            #pragma unroll
            for (int k = 0; k < K_; k++) {
                acc[k] += ph * wp[k * 32] + m * wp[(5 + k) * 32] + p * wp[(15 + k) * 32];
                sb[k]  += m * wp[(10 + k) * 32];
            }
        }
        float sm  = wsum(lsm);
        float sm2 = wsum(lsm2);
        float sfm = wsum(lsfm);
        float pk  = wmax(lpk);
        float sur = wsum(lur);
        float sui = wsum(lui);

        __syncwarp();
        // ---- ordered cumsum of mag for rolloff/median (warp scan) ----
        float cs[8];
        float run = 0.0f;
        #pragma unroll
        for (int q = 0; q < 8; q++) {
            run += smg[spad(8 * lane + q)];
            cs[q] = run;
        }
        float incl = run;
        #pragma unroll
        for (int o = 1; o < 32; o <<= 1) {
            float vv = __shfl_up_sync(0xffffffffu, incl, o);
            if (lane >= o) incl += vv;
        }
        float excl  = incl - run;
        float total = __shfl_sync(0xffffffffu, incl, 31);
        float thr1 = 0.85f * total, thr2 = 0.5f * total;
        int cand1 = 1 << 30, cand2 = 1 << 30;
        #pragma unroll
        for (int q = 7; q >= 0; q--) {
            float v = excl + cs[q];
            if (v >= thr1) cand1 = 8 * lane + q;
            if (v >= thr2) cand2 = 8 * lane + q;
        }
        int rolli = wminI(cand1);
        int medi  = wminI(cand2);

        // ---- Hilbert FFT: input conj(X*h) in natural order from smem Z ----
        #pragma unroll
        for (int j = 0; j < 8; j++) {
            int n = lane + 32 * j;
            int mn_ = (256 - n) & 255;
            float Zr = szr[spad(n)],   Zi = szi[spad(n)];
            float Mr = szr[spad(mn_)], Mi = szi[spad(mn_)];
            float Xr = 0.5f * (Zr + Mr);
            float Xi = 0.5f * (Zi - Mi);
            float h = (n == 0 || n == 128) ? 1.0f : ((n < 128) ? 2.0f : 0.0f);
            z[j].x =  Xr * h;
            z[j].y = -Xi * h;
        }
        __syncwarp();   // smem reads done before next iteration's scatter
        fft256w(z, tw2r, tw2i, tw5r, tw5i, lane);
        float la = 0, la2 = 0;
        #pragma unroll
        for (int j = 0; j < 8; j++) {
            float a2 = (z[j].x * z[j].x + z[j].y * z[j].y) * (1.0f / 65536.0f);
            float rs = (a2 > 0.0f) ? rsqrtf(a2) : 0.0f;
            la += a2 * rs; la2 += a2;
        }
        float sa  = wsum(la);
        float sa2 = wsum(la2);

        // ---- fold bicoh normalization, reduce accumulators ----
        float invn = rsqrtf(sm2);
        #pragma unroll
        for (int k = 0; k < K_; k++) acc[k] = wsum(acc[k] + invn * sb[k]);

        if (lane == 0) {
            float pc   = sqrtf(sur * sur + sui * sui) * (1.0f / 256.0f);
            float cen  = sfm / sm;
            float rol  = (float)rolli;
            float avg  = sm * (1.0f / 256.0f);
            float medf = (medi < 128) ? (float)medi : (float)(medi - 256);
            float ma   = sa * (1.0f / 256.0f);
            float amp  = sqrtf(fmaxf(sa2 * (1.0f / 256.0f) - ma * ma, 0.0f));
            #pragma unroll
            for (int k = 0; k < K_; k++) {
                float v = acc[k]
                        + pc   * W[k * FC_ + 256 * C_ + c]
                        + cen  * W[k * FC_ + 769 * C_ + c]
                        + rol  * W[k * FC_ + 770 * C_ + c]
                        + pk   * W[k * FC_ + 771 * C_ + c]
                        + avg  * W[k * FC_ + 772 * C_ + c]
                        + medf * W[k * FC_ + 902 * C_ + c]
                        + amp  * W[k * FC_ + 903 * C_ + c];
                g_part[(c * B_ + b) * K_ + k] = v;
            }
        }
    }
}

// ---------------------------------------------------------------------------
// Kernel 4: reduce partials over channels + bias. One block per b.
// ---------------------------------------------------------------------------
__global__ void reduceK(const float* __restrict__ bias, float* __restrict__ out) {
    __shared__ float s[320];
    int b = blockIdx.x;
    int tid = threadIdx.x;                 // 320 threads
    int c = tid / 5, k = tid - 5 * c;
    s[tid] = g_part[(c * B_ + b) * K_ + k];
    __syncthreads();
    #pragma unroll
    for (int st = 160; st >= 5; st >>= 1) {
        if (tid < st) s[tid] += s[tid + st];
        __syncthreads();
    }
    if (tid < 5) out[b * K_ + tid] = s[tid] + bias[tid];
}

// ---------------------------------------------------------------------------
extern "C" void kernel_launch(void* const* d_in, const int* in_sizes, int n_in,
                              void* d_out, int out_size) {
    const float* x    = (const float*)d_in[0];   // (1024,256,64)
    // d_in[1] = x_mark_enc, unused
    const float* W    = (const float*)d_in[2];   // (5, 57856)
    const float* bias = (const float*)d_in[3];   // (5,)
    float* out = (float*)d_out;                  // (1024,5)

    buildW4<<<(C_ * 8 * 20 * 32 + 255) / 256, 256>>>(W);
    transposeX<<<dim3(T_ / 32, C_ / 32, B_), dim3(32, 8)>>>(x);
    mainK<<<dim3(C_, 32), 128>>>(W);
    reduceK<<<B_, 320>>>(bias, out);
}